// round 10
// baseline (speedup 1.0000x reference)
#include <cuda_runtime.h>

#define NG   512
#define S    128
#define FSCALE_ENC 536870912.0   // 2^29 encode grain
#define FSCALE_DEC 268435456.0   // 2^28 decode: /2 gap = pair-symmetry x2

__device__ unsigned long long g_acc   = 0ULL;
__device__ unsigned           g_count = 0u;

// 512 CTAs x 256 threads (CTA = one group).
// Phase 1 (no dependent DRAM chain): all 256 threads stream the group's TWO
//   contiguous 9KB coordinate windows (rows g*256..g*256+255, 36B/row, 16B
//   aligned) into SMEM via coalesced LDG.128 (4.5 float4/thread, MLP~5),
//   while threads<128 concurrently load positions (speculative int32 view;
//   per-warp ballot on odd dwords 129..191 — group-1 indices nonzero iff
//   int32, zero int64 high-halves iff int64 — resolves dtype with no extra
//   sync; int64 view reloaded only on that path).
// Phase 2: gather CA rows from SMEM (LDS, 29cyc) into compact A/B arrays
//   (float4(x0,x1,x2,t0) + float2(t1,t2)); rows 0..63 duplicated so the
//   d-loop needs no wraparound.
// Phase 3 (= round-7 compute, measured best): thread (row=t&127, h=t>>7)
//   covers d in [1+32h, 32+32h]; each unordered pair once (d=64 weighted by
//   row<64). (sqrt a - sqrt b)^2 = a+b-2*sqrt(ab), sqrt.approx (sqrt(0)=0
//   matches the grad-safe pdist).
// Tail: fixed-point u64 red.release (associative => deterministic),
//   acq_rel counter, last CTA writes mean + resets globals.
__global__ void __launch_bounds__(256)
loss_kernel(const float* __restrict__ inputs,
            const float* __restrict__ target,
            const void*  __restrict__ positions,
            float* __restrict__ out) {
    __shared__ float4 win[1152];        // [0:576) inputs window, [576:1152) target
    __shared__ float4 A[S + 64];
    __shared__ float2 B[S + 64];
    __shared__ float  wsum[8];

    const int tid = threadIdx.x;
    const int g   = blockIdx.x;
    const int row = tid & (S - 1);
    const int h   = tid >> 7;

    // ---- positions + dtype (threads < 128 only; no cross-warp sync) ----
    int p_local = 0;
    if (tid < S) {
        const unsigned* pw = (const unsigned*)positions;
        const unsigned p32 = pw[g * S + tid];                    // speculative
        const unsigned chk = pw[129 + 2 * (tid & 31)];           // <1KB, safe
        const unsigned any = __ballot_sync(0xffffffffu, chk != 0u);
        int p = (int)p32;
        if (any == 0u)                                           // int64
            p = (int)((const long long*)positions)[g * S + tid];
        p_local = p & 255;                                       // row in window
    }

    // ---- stream both 9KB windows (576 float4 each), coalesced ----
    {
        const float4* gi = (const float4*)(inputs + (size_t)g * 2304);
        const float4* gt = (const float4*)(target + (size_t)g * 2304);
        win[tid]        = gi[tid];
        win[tid + 256]  = gi[tid + 256];
        win[tid + 576]  = gt[tid];
        win[tid + 832]  = gt[tid + 256];
        if (tid < 64) {
            win[tid + 512]  = gi[tid + 512];
            win[tid + 1088] = gt[tid + 512];
        }
    }
    __syncthreads();

    // ---- gather CA rows from SMEM into compact layout ----
    if (tid < S) {
        const float* wf = (const float*)win;
        const float* xr = wf + p_local * 9 + 3;          // CA = frame row 1
        const float* tr = wf + 2304 + p_local * 9 + 3;
        const float4 av = make_float4(xr[0], xr[1], xr[2], tr[0]);
        const float2 bv = make_float2(tr[1], tr[2]);
        A[tid] = av;  B[tid] = bv;
        if (tid < 64) { A[tid + S] = av; B[tid + S] = bv; }
    }
    __syncthreads();

    // ---- pair loop (round-7): d = 1+32h .. 32+32h, j = row + d ----
    const float4 av = A[row];
    const float2 bv = B[row];
    const float4* qa = &A[row + 1 + 32 * h];
    const float2* qb = &B[row + 1 + 32 * h];
    const float xi0 = av.x, xi1 = av.y, xi2 = av.z;
    const float ti0 = av.w, ti1 = bv.x, ti2 = bv.y;
    const float wLast = (h == 1 && row >= 64) ? 0.0f : 1.0f;  // d=64 pair once

    float accA = 0.f, accB = 0.f, accSq = 0.f;
#pragma unroll
    for (int jj = 0; jj < 32; ++jj) {
        const float4 va = qa[jj];
        const float2 vb = qb[jj];
        const float dx0 = va.x - xi0, dx1 = va.y - xi1, dx2 = va.z - xi2;
        const float a = dx0 * dx0 + dx1 * dx1 + dx2 * dx2;
        const float dt0 = va.w - ti0, dt1 = vb.x - ti1, dt2 = vb.y - ti2;
        const float b = dt0 * dt0 + dt1 * dt1 + dt2 * dt2;
        float sq;
        asm("sqrt.approx.f32 %0, %1;" : "=f"(sq) : "f"(a * b));
        if (jj == 31) {
            accA += a * wLast; accB += b * wLast; accSq += sq * wLast;
        } else {
            accA += a; accB += b; accSq += sq;
        }
    }
    float acc = (accA + accB) - 2.0f * accSq;

    // ---- block reduction (8 warps) ----
#pragma unroll
    for (int off = 16; off > 0; off >>= 1)
        acc += __shfl_xor_sync(0xffffffffu, acc, off);
    const int lane = tid & 31, warp = tid >> 5;
    if (lane == 0) wsum[warp] = acc;
    __syncthreads();

    // ---- fixed-point global accumulate + last-CTA finish ----
    if (tid == 0) {
        float s = 0.0f;
#pragma unroll
        for (int w = 0; w < 8; ++w) s += wsum[w];
        const long long fx = (long long)((double)s * FSCALE_ENC);
        asm volatile("red.release.gpu.add.u64 [%0], %1;"
                     :: "l"(&g_acc), "l"((unsigned long long)fx) : "memory");
        unsigned old;
        asm volatile("atom.acq_rel.gpu.add.u32 %0, [%1], 1;"
                     : "=r"(old) : "l"(&g_count) : "memory");
        if (old == NG - 1) {
            unsigned long long tot;
            asm volatile("ld.acquire.gpu.u64 %0, [%1];"
                         : "=l"(tot) : "l"(&g_acc) : "memory");
            out[0] = (float)((double)(long long)tot / FSCALE_DEC
                             / ((double)NG * S * S));
            g_acc   = 0ULL;   // reset for next graph replay
            g_count = 0u;
        }
    }
}

extern "C" void kernel_launch(void* const* d_in, const int* in_sizes, int n_in,
                              void* d_out, int out_size) {
    const float* inputs    = (const float*)d_in[0];
    const float* target    = (const float*)d_in[1];
    const void*  positions = d_in[2];
    loss_kernel<<<NG, 256>>>(inputs, target, positions, (float*)d_out);
}

// round 11
// speedup vs baseline: 1.1866x; 1.1866x over previous
#include <cuda_runtime.h>

#define NG   512
#define S    128
#define FENC 16777216.0          // 2^24 fixed-point encode grain
#define FDEC 8388608.0           // 2^23 decode: /2 gap applies pair-symmetry x2
#define CNT_BIT 54
#define SUM_MASK ((1ULL << CNT_BIT) - 1ULL)

__device__ unsigned long long g_acc = 0ULL;   // bits[0,54): fx sum, bits[54+): count

// 512 CTAs x 256 threads (CTA = one group). Round-7 champion gather+compute.
//  * dtype detection per-warp (no sync, no smem flag): odd dwords 129..191
//    (<1KB, safe under both layouts; L1/L2 broadcast) are group-1 indices
//    (>=256, nonzero) iff int32; zero int64 high-halves iff int64.
//  * int32-view positions load speculative (always in bounds); int64 view
//    reloaded only on the confirmed int64 path.
//  * threads<128 gather CA coords (frame row 1 -> float offset p*9+3) into
//    SMEM float4(x0,x1,x2,t0) + float2(t1,t2); rows 0..63 duplicated so the
//    d-loop needs no wraparound (immediate LDS offsets).
//  * thread (row=t&127, h=t>>7) covers d in [1+32h, 32+32h]; each unordered
//    pair once (d=64 weighted by row<64). (sqrt a - sqrt b)^2 = a+b-2*sqrt(ab)
//    via sqrt.approx (sqrt(0)=0 matches the grad-safe pdist).
//  * tail: ONE relaxed u64 atomicAdd carrying {fx partial, arrival count}.
//    Integer adds are associative => deterministic. Partial is nonnegative
//    (sum of squares; clamped at 0 for paranoia) so no borrow into the count
//    field. Last CTA: total = (old & MASK) + own fx; write mean; reset.
__global__ void __launch_bounds__(256)
loss_kernel(const float* __restrict__ inputs,
            const float* __restrict__ target,
            const void*  __restrict__ positions,
            float* __restrict__ out) {
    __shared__ float4 A[S + 64];
    __shared__ float2 B[S + 64];
    __shared__ float  wsum[8];

    const int tid = threadIdx.x;
    const int g   = blockIdx.x;
    const int row = tid & (S - 1);
    const int h   = tid >> 7;

    // ---- positions + per-warp dtype detection (threads < 128) ----
    if (tid < S) {
        const unsigned* pw = (const unsigned*)positions;
        const unsigned p32 = pw[g * S + tid];                 // speculative
        const unsigned chk = pw[129 + 2 * (tid & 31)];        // <1KB, safe
        const unsigned any = __ballot_sync(0xffffffffu, chk != 0u);
        int p = (int)p32;
        if (any == 0u)                                        // int64 layout
            p = (int)((const long long*)positions)[g * S + tid];

        // ---- gather CA coords ----
        const float* xr = inputs + (size_t)p * 9 + 3;
        const float* tr = target + (size_t)p * 9 + 3;
        const float4 av = make_float4(xr[0], xr[1], xr[2], tr[0]);
        const float2 bv = make_float2(tr[1], tr[2]);
        A[tid] = av;  B[tid] = bv;
        if (tid < 64) { A[tid + S] = av; B[tid + S] = bv; }
    }
    __syncthreads();

    // ---- pair loop: d = 1+32h .. 32+32h, j = row + d (no wrap) ----
    const float4 av = A[row];
    const float2 bv = B[row];
    const float4* qa = &A[row + 1 + 32 * h];
    const float2* qb = &B[row + 1 + 32 * h];
    const float xi0 = av.x, xi1 = av.y, xi2 = av.z;
    const float ti0 = av.w, ti1 = bv.x, ti2 = bv.y;
    const float wLast = (h == 1 && row >= 64) ? 0.0f : 1.0f;  // d=64 pair once

    float accA = 0.f, accB = 0.f, accSq = 0.f;
#pragma unroll
    for (int jj = 0; jj < 32; ++jj) {
        const float4 va = qa[jj];
        const float2 vb = qb[jj];
        const float dx0 = va.x - xi0, dx1 = va.y - xi1, dx2 = va.z - xi2;
        const float a = dx0 * dx0 + dx1 * dx1 + dx2 * dx2;
        const float dt0 = va.w - ti0, dt1 = vb.x - ti1, dt2 = vb.y - ti2;
        const float b = dt0 * dt0 + dt1 * dt1 + dt2 * dt2;
        float sq;
        asm("sqrt.approx.f32 %0, %1;" : "=f"(sq) : "f"(a * b));
        if (jj == 31) {
            accA += a * wLast; accB += b * wLast; accSq += sq * wLast;
        } else {
            accA += a; accB += b; accSq += sq;
        }
    }
    float acc = (accA + accB) - 2.0f * accSq;

    // ---- block reduction (8 warps) ----
#pragma unroll
    for (int off = 16; off > 0; off >>= 1)
        acc += __shfl_xor_sync(0xffffffffu, acc, off);
    const int lane = tid & 31, warp = tid >> 5;
    if (lane == 0) wsum[warp] = acc;
    __syncthreads();

    // ---- single-atomic tail (tid 0 only) ----
    if (tid == 0) {
        float s = 0.0f;
#pragma unroll
        for (int w = 0; w < 8; ++w) s += wsum[w];
        s = fmaxf(s, 0.0f);                       // guard the count field
        const unsigned long long fx =
            (unsigned long long)(long long)((double)s * FENC);
        const unsigned long long add = fx + (1ULL << CNT_BIT);
        const unsigned long long old = atomicAdd(&g_acc, add);
        if ((old >> CNT_BIT) == (unsigned long long)(NG - 1)) {
            const unsigned long long tot = (old & SUM_MASK) + fx;
            out[0] = (float)((double)tot / FDEC / ((double)NG * S * S));
            g_acc = 0ULL;                          // reset for next replay
        }
    }
}

extern "C" void kernel_launch(void* const* d_in, const int* in_sizes, int n_in,
                              void* d_out, int out_size) {
    const float* inputs    = (const float*)d_in[0];
    const float* target    = (const float*)d_in[1];
    const void*  positions = d_in[2];
    loss_kernel<<<NG, 256>>>(inputs, target, positions, (float*)d_out);
}